// round 6
// baseline (speedup 1.0000x reference)
#include <cuda_runtime.h>

#define B   16
#define KV  8192
#define D   1024
#define D4  256        // D / 4 (float4 per row)
#define DH4 128        // half-D in float4
#define NSPLIT 64      // KV splits
#define KPS (KV / NSPLIT)   // 128 keys per split

// ---------------- device scratch ----------------
__device__ float g_qp [2 * B * D];            // q partials (K-halves)
__device__ float g_nkp[2 * B * D];            // new_k partials
__device__ float g_nvp[2 * B * D];            // new_v partials
__device__ float g_partial[B * NSPLIT * D];   // 4 MB, unnormalized V partials
__device__ float g_m[B * NSPLIT];             // local maxima
__device__ float g_l[B * NSPLIT];             // local exp-sums

// ---------------- K0: split-K projections, all 16 batches per block ----------------
// grid (384, 2), block 128 (4 warps). Each warp: 2 rows x 16 batches x half-K.
// Weights are read exactly once across the whole grid.
__global__ void __launch_bounds__(128, 6)
proj_kernel(const float* __restrict__ x,
            const float* __restrict__ wq,
            const float* __restrict__ wk,
            const float* __restrict__ wv) {
    __shared__ float4 xs[B * DH4];   // 16 batches, half of x each: 32 KB
    const int tid  = threadIdx.x;
    const int warp = tid >> 5;
    const int lane = tid & 31;
    const int kh   = blockIdx.y;     // K half (0 or 1)

    const float4* x4 = (const float4*)x;
    for (int i = tid; i < B * DH4; i += 128) {
        const int b = i >> 7, c = i & 127;
        xs[i] = x4[b * D4 + kh * DH4 + c];
    }
    __syncthreads();

    const int rowA = blockIdx.x * 8 + warp * 2;   // 0..3070 (even)
    const int rowB = rowA + 1;
    const int matA = rowA >> 10, eA = rowA & 1023;
    const int matB = rowB >> 10, eB = rowB & 1023;
    const float* WA  = (matA == 0) ? wq   : (matA == 1) ? wk    : wv;
    const float* WB  = (matB == 0) ? wq   : (matB == 1) ? wk    : wv;
    float*      outA = (matA == 0) ? g_qp : (matA == 1) ? g_nkp : g_nvp;
    float*      outB = (matB == 0) ? g_qp : (matB == 1) ? g_nkp : g_nvp;
    const float4* WA4 = (const float4*)WA + (size_t)eA * D4 + kh * DH4;
    const float4* WB4 = (const float4*)WB + (size_t)eB * D4 + kh * DH4;

    float accA[B], accB[B];
#pragma unroll
    for (int b = 0; b < B; b++) { accA[b] = 0.f; accB[b] = 0.f; }

#pragma unroll
    for (int ii = 0; ii < 4; ii++) {
        const int i = lane + ii * 32;
        const float4 wa = WA4[i];
        const float4 wb = WB4[i];
#pragma unroll
        for (int b = 0; b < B; b++) {
            const float4 xv = xs[b * DH4 + i];
            accA[b] += wa.x * xv.x + wa.y * xv.y + wa.z * xv.z + wa.w * xv.w;
            accB[b] += wb.x * xv.x + wb.y * xv.y + wb.z * xv.z + wb.w * xv.w;
        }
    }
#pragma unroll
    for (int b = 0; b < B; b++) {
#pragma unroll
        for (int o = 16; o > 0; o >>= 1) {
            accA[b] += __shfl_xor_sync(0xffffffffu, accA[b], o);
            accB[b] += __shfl_xor_sync(0xffffffffu, accB[b], o);
        }
    }
    if (lane == 0) {
#pragma unroll
        for (int b = 0; b < B; b++) {
            outA[(kh * B + b) * D + eA] = accA[b];
            outB[(kh * B + b) * D + eB] = accB[b];
        }
    }
}

// ---------------- K1: fused scores + local softmax + weighted AV partial ----------------
// grid (NSPLIT, B), block 256 (8 warps). Each block: 128 keys of one batch.
__global__ void attn_kernel(const float* __restrict__ cache_k,
                            const float* __restrict__ cache_v) {
    const int split = blockIdx.x;
    const int b     = blockIdx.y;
    const int tid   = threadIdx.x;
    const int warp  = tid >> 5;
    const int lane  = tid & 31;
    const int key0  = split * KPS;

    __shared__ float4 qs[D4];       // 4 KB
    __shared__ float  ss[KPS];      // scores -> exp weights
    __shared__ float  wred[8];

    // combine q halves
    {
        const float4* qp = (const float4*)g_qp;
        const float4 a = qp[b * D4 + tid];
        const float4 c = qp[(B + b) * D4 + tid];
        qs[tid] = make_float4(a.x + c.x, a.y + c.y, a.z + c.z, a.w + c.w);
    }
    __syncthreads();

    // ---- phase 1: scores for 128 keys (16 per warp, 2-key ILP) ----
    const float4* K4 = (const float4*)cache_k;
    const int kw0 = warp * 16;
#pragma unroll 1
    for (int j = 0; j < 8; j++) {
        const int kA = kw0 + j;
        const int kB = kA + 8;
        const float4* rowA = K4 + (size_t)(b * KV + key0 + kA) * D4;
        const float4* rowB = K4 + (size_t)(b * KV + key0 + kB) * D4;
        float aA = 0.f, aB = 0.f;
#pragma unroll
        for (int ii = 0; ii < 8; ii++) {
            const int i = lane + ii * 32;
            const float4 qq = qs[i];
            const float4 ka = rowA[i];
            const float4 kb = rowB[i];
            aA += ka.x * qq.x + ka.y * qq.y + ka.z * qq.z + ka.w * qq.w;
            aB += kb.x * qq.x + kb.y * qq.y + kb.z * qq.z + kb.w * qq.w;
        }
#pragma unroll
        for (int o = 16; o > 0; o >>= 1) {
            aA += __shfl_xor_sync(0xffffffffu, aA, o);
            aB += __shfl_xor_sync(0xffffffffu, aB, o);
        }
        if (lane == 0) {
            ss[kA] = aA * 0.03125f;   // 1/sqrt(1024)
            ss[kB] = aB * 0.03125f;
        }
    }
    __syncthreads();

    // ---- local softmax stats: m = max, l = sum exp(s-m); exp stored in ss ----
    float mv = (tid < KPS) ? ss[tid] : -1e30f;
#pragma unroll
    for (int o = 16; o > 0; o >>= 1)
        mv = fmaxf(mv, __shfl_xor_sync(0xffffffffu, mv, o));
    if (lane == 0) wred[warp] = mv;
    __syncthreads();
    if (tid == 0) {
        float m = wred[0];
#pragma unroll
        for (int w = 1; w < 8; w++) m = fmaxf(m, wred[w]);
        wred[0] = m;
    }
    __syncthreads();
    const float m = wred[0];
    __syncthreads();

    float ev = 0.f;
    if (tid < KPS) {
        const float e = __expf(ss[tid] - m);
        ss[tid] = e;
        ev = e;
    }
#pragma unroll
    for (int o = 16; o > 0; o >>= 1)
        ev += __shfl_xor_sync(0xffffffffu, ev, o);
    if (lane == 0) wred[warp] = ev;
    __syncthreads();
    if (tid == 0) {
        float l = 0.f;
#pragma unroll
        for (int w = 0; w < 8; w++) l += wred[w];
        g_m[b * NSPLIT + split] = m;
        g_l[b * NSPLIT + split] = l;
    }
    __syncthreads();

    // ---- phase 2: partial = sum_k exp(s_k - m) * v[k][:] ----
    const float4* V4 = (const float4*)cache_v;
    const float4* base = V4 + (size_t)(b * KV + key0) * D4 + tid;
    float4 acc = make_float4(0.f, 0.f, 0.f, 0.f);
#pragma unroll 16
    for (int k = 0; k < KPS; k++) {
        const float  w = ss[k];
        const float4 v = base[(size_t)k * D4];
        acc.x += w * v.x; acc.y += w * v.y;
        acc.z += w * v.z; acc.w += w * v.w;
    }
    ((float4*)g_partial)[(size_t)(b * NSPLIT + split) * D4 + tid] = acc;
}

// ---------------- K2: global rescale + new-token term + round ----------------
// grid (4, B), block 256. Block covers 64 float4 columns; thread quads split NSPLIT.
__global__ void reduce_kernel(float* __restrict__ out) {
    const int b    = blockIdx.y;
    const int tid  = threadIdx.x;
    const int quad = tid >> 6;                    // 0..3  (16 splits each)
    const int c    = tid & 63;                    // local column
    const int col  = blockIdx.x * 64 + c;         // float4 column 0..255

    __shared__ float  red[256];
    __shared__ float  sc[NSPLIT];
    __shared__ float  s_wn;
    __shared__ float4 part[4][64];

    // new-key score: q . new_k / sqrt(D) from combined halves
    {
        const float4* qp  = (const float4*)g_qp;
        const float4* nkp = (const float4*)g_nkp;
        const float4 q0 = qp [b * D4 + tid], q1 = qp [(B + b) * D4 + tid];
        const float4 k0 = nkp[b * D4 + tid], k1 = nkp[(B + b) * D4 + tid];
        const float qx = q0.x + q1.x, qy = q0.y + q1.y, qz = q0.z + q1.z, qw = q0.w + q1.w;
        const float kx = k0.x + k1.x, ky = k0.y + k1.y, kz = k0.z + k1.z, kw = k0.w + k1.w;
        red[tid] = qx * kx + qy * ky + qz * kz + qw * kw;
    }
    __syncthreads();
    for (int s = 128; s > 0; s >>= 1) {
        if (tid < s) red[tid] += red[tid + s];
        __syncthreads();
    }
    const float s_new = red[0] * 0.03125f;

    if (tid == 0) {
        float M = s_new;
#pragma unroll
        for (int s = 0; s < NSPLIT; s++) M = fmaxf(M, g_m[b * NSPLIT + s]);
        float L = __expf(s_new - M);
#pragma unroll
        for (int s = 0; s < NSPLIT; s++) {
            const float e = __expf(g_m[b * NSPLIT + s] - M);
            sc[s] = e;
            L += g_l[b * NSPLIT + s] * e;
        }
        const float inv = 1.f / L;
#pragma unroll
        for (int s = 0; s < NSPLIT; s++) sc[s] *= inv;
        s_wn = __expf(s_new - M) * inv;
    }
    __syncthreads();

    // each quad sums 16 splits for its column
    const float4* P4 = (const float4*)g_partial + (size_t)b * NSPLIT * D4 + col;
    float4 acc = make_float4(0.f, 0.f, 0.f, 0.f);
#pragma unroll
    for (int j = 0; j < 16; j++) {
        const int s = quad * 16 + j;
        const float  w = sc[s];
        const float4 p = P4[(size_t)s * D4];
        acc.x += w * p.x; acc.y += w * p.y;
        acc.z += w * p.z; acc.w += w * p.w;
    }
    part[quad][c] = acc;
    __syncthreads();

    if (quad == 0) {
        float4 a = part[0][c], p1 = part[1][c], p2 = part[2][c], p3 = part[3][c];
        a.x += p1.x + p2.x + p3.x;
        a.y += p1.y + p2.y + p3.y;
        a.z += p1.z + p2.z + p3.z;
        a.w += p1.w + p2.w + p3.w;

        // new-v term from combined halves
        const float wn = s_wn;
        const float4* nvp = (const float4*)g_nvp;
        const float4 v0 = nvp[b * D4 + col], v1 = nvp[(B + b) * D4 + col];
        a.x += wn * (v0.x + v1.x); a.y += wn * (v0.y + v1.y);
        a.z += wn * (v0.z + v1.z); a.w += wn * (v0.w + v1.w);

        a.x = rintf(a.x * 10000.f) / 10000.f;
        a.y = rintf(a.y * 10000.f) / 10000.f;
        a.z = rintf(a.z * 10000.f) / 10000.f;
        a.w = rintf(a.w * 10000.f) / 10000.f;
        ((float4*)out)[b * D4 + col] = a;
    }
}

// ---------------- launcher ----------------
extern "C" void kernel_launch(void* const* d_in, const int* in_sizes, int n_in,
                              void* d_out, int out_size) {
    const float* x  = (const float*)d_in[0];
    const float* ck = (const float*)d_in[1];
    const float* cv = (const float*)d_in[2];
    const float* wq = (const float*)d_in[3];
    const float* wk = (const float*)d_in[4];
    const float* wv = (const float*)d_in[5];
    float* out = (float*)d_out;

    proj_kernel  <<<dim3(384, 2), 128>>>(x, wq, wk, wv);
    attn_kernel  <<<dim3(NSPLIT, B), 256>>>(ck, cv);
    reduce_kernel<<<dim3(4, B), 256>>>(out);
}

// round 7
// speedup vs baseline: 1.0177x; 1.0177x over previous
#include <cuda_runtime.h>

#define B   16
#define KV  8192
#define D   1024
#define D4  256        // D / 4 (float4 per row)
#define NSPLIT 64      // KV splits
#define KPS (KV / NSPLIT)   // 128 keys per split

// ---------------- device scratch ----------------
__device__ float g_q [B * D];
__device__ float g_nk[B * D];
__device__ float g_nv[B * D];
__device__ float g_partial[B * NSPLIT * D];   // 4 MB, unnormalized V partials
__device__ float g_m[B * NSPLIT];             // local maxima
__device__ float g_l[B * NSPLIT];             // local exp-sums

// ---------------- stream/event for fork-join (created once, not device mem) ----
static cudaStream_t g_s2;
static cudaEvent_t  g_ev_fork, g_ev_join;
static struct StreamInit {
    StreamInit() {
        cudaStreamCreateWithFlags(&g_s2, cudaStreamNonBlocking);
        cudaEventCreateWithFlags(&g_ev_fork, cudaEventDisableTiming);
        cudaEventCreateWithFlags(&g_ev_join, cudaEventDisableTiming);
    }
} g_stream_init;

// ---------------- K0a: q projection (wq only) ----------------
// grid (64, 2), block 256 (8 warps). Each warp: 2 rows x 8 batches.
__global__ void q_proj_kernel(const float* __restrict__ x,
                              const float* __restrict__ wq) {
    __shared__ float4 xs[8 * D4];   // 8 batches of x, 32 KB
    const int tid  = threadIdx.x;
    const int warp = tid >> 5;
    const int lane = tid & 31;
    const int grp  = blockIdx.y;

    const float4* x4 = (const float4*)x;
    for (int i = tid; i < 8 * D4; i += 256) xs[i] = x4[grp * 8 * D4 + i];
    __syncthreads();

    const int eA = blockIdx.x * 16 + warp * 2;   // 0..1022 (even)
    const int eB = eA + 1;
    const float4* WA4 = (const float4*)wq + (size_t)eA * D4;
    const float4* WB4 = (const float4*)wq + (size_t)eB * D4;

    float accA[8], accB[8];
#pragma unroll
    for (int b = 0; b < 8; b++) { accA[b] = 0.f; accB[b] = 0.f; }

#pragma unroll
    for (int ii = 0; ii < 8; ii++) {
        const int i = lane + ii * 32;
        const float4 wa = WA4[i];
        const float4 wb = WB4[i];
#pragma unroll
        for (int b = 0; b < 8; b++) {
            const float4 xv = xs[b * D4 + i];
            accA[b] += wa.x * xv.x + wa.y * xv.y + wa.z * xv.z + wa.w * xv.w;
            accB[b] += wb.x * xv.x + wb.y * xv.y + wb.z * xv.z + wb.w * xv.w;
        }
    }
#pragma unroll
    for (int b = 0; b < 8; b++) {
#pragma unroll
        for (int o = 16; o > 0; o >>= 1) {
            accA[b] += __shfl_xor_sync(0xffffffffu, accA[b], o);
            accB[b] += __shfl_xor_sync(0xffffffffu, accB[b], o);
        }
    }
    if (lane == 0) {
#pragma unroll
        for (int b = 0; b < 8; b++) {
            g_q[(grp * 8 + b) * D + eA] = accA[b];
            g_q[(grp * 8 + b) * D + eB] = accB[b];
        }
    }
}

// ---------------- K0b: k/v projections (wk, wv) — runs concurrent with attn ----
// grid (128, 2), block 256 (8 warps). Each warp: 2 rows x 8 batches.
__global__ void kv_proj_kernel(const float* __restrict__ x,
                               const float* __restrict__ wk,
                               const float* __restrict__ wv) {
    __shared__ float4 xs[8 * D4];   // 8 batches of x, 32 KB
    const int tid  = threadIdx.x;
    const int warp = tid >> 5;
    const int lane = tid & 31;
    const int grp  = blockIdx.y;

    const float4* x4 = (const float4*)x;
    for (int i = tid; i < 8 * D4; i += 256) xs[i] = x4[grp * 8 * D4 + i];
    __syncthreads();

    const int rowA = blockIdx.x * 16 + warp * 2;   // 0..2046 (even)
    const int rowB = rowA + 1;
    const int matA = rowA >> 10, eA = rowA & 1023;
    const int matB = rowB >> 10, eB = rowB & 1023;
    const float* WA  = (matA == 0) ? wk   : wv;
    const float* WB  = (matB == 0) ? wk   : wv;
    float*      outA = (matA == 0) ? g_nk : g_nv;
    float*      outB = (matB == 0) ? g_nk : g_nv;
    const float4* WA4 = (const float4*)WA + (size_t)eA * D4;
    const float4* WB4 = (const float4*)WB + (size_t)eB * D4;

    float accA[8], accB[8];
#pragma unroll
    for (int b = 0; b < 8; b++) { accA[b] = 0.f; accB[b] = 0.f; }

#pragma unroll
    for (int ii = 0; ii < 8; ii++) {
        const int i = lane + ii * 32;
        const float4 wa = WA4[i];
        const float4 wb = WB4[i];
#pragma unroll
        for (int b = 0; b < 8; b++) {
            const float4 xv = xs[b * D4 + i];
            accA[b] += wa.x * xv.x + wa.y * xv.y + wa.z * xv.z + wa.w * xv.w;
            accB[b] += wb.x * xv.x + wb.y * xv.y + wb.z * xv.z + wb.w * xv.w;
        }
    }
#pragma unroll
    for (int b = 0; b < 8; b++) {
#pragma unroll
        for (int o = 16; o > 0; o >>= 1) {
            accA[b] += __shfl_xor_sync(0xffffffffu, accA[b], o);
            accB[b] += __shfl_xor_sync(0xffffffffu, accB[b], o);
        }
    }
    if (lane == 0) {
#pragma unroll
        for (int b = 0; b < 8; b++) {
            outA[(grp * 8 + b) * D + eA] = accA[b];
            outB[(grp * 8 + b) * D + eB] = accB[b];
        }
    }
}

// ---------------- K1: fused scores + local softmax + weighted AV partial ----------------
// grid (NSPLIT, B), block 256 (8 warps). Each block: 128 keys of one batch.
__global__ void attn_kernel(const float* __restrict__ cache_k,
                            const float* __restrict__ cache_v) {
    const int split = blockIdx.x;
    const int b     = blockIdx.y;
    const int tid   = threadIdx.x;
    const int warp  = tid >> 5;
    const int lane  = tid & 31;
    const int key0  = split * KPS;

    __shared__ float4 qs[D4];       // 4 KB
    __shared__ float  ss[KPS];      // scores -> exp weights
    __shared__ float  wred[8];

    qs[tid] = ((const float4*)g_q)[b * D4 + tid];
    __syncthreads();

    // ---- phase 1: scores for 128 keys (16 per warp, 2-key ILP) ----
    const float4* K4 = (const float4*)cache_k;
    const int kw0 = warp * 16;
#pragma unroll 1
    for (int j = 0; j < 8; j++) {
        const int kA = kw0 + j;
        const int kB = kA + 8;
        const float4* rowA = K4 + (size_t)(b * KV + key0 + kA) * D4;
        const float4* rowB = K4 + (size_t)(b * KV + key0 + kB) * D4;
        float aA = 0.f, aB = 0.f;
#pragma unroll
        for (int ii = 0; ii < 8; ii++) {
            const int i = lane + ii * 32;
            const float4 qq = qs[i];
            const float4 ka = rowA[i];
            const float4 kb = rowB[i];
            aA += ka.x * qq.x + ka.y * qq.y + ka.z * qq.z + ka.w * qq.w;
            aB += kb.x * qq.x + kb.y * qq.y + kb.z * qq.z + kb.w * qq.w;
        }
#pragma unroll
        for (int o = 16; o > 0; o >>= 1) {
            aA += __shfl_xor_sync(0xffffffffu, aA, o);
            aB += __shfl_xor_sync(0xffffffffu, aB, o);
        }
        if (lane == 0) {
            ss[kA] = aA * 0.03125f;   // 1/sqrt(1024)
            ss[kB] = aB * 0.03125f;
        }
    }
    __syncthreads();

    // ---- local softmax stats: m = max, l = sum exp(s-m); exp stored in ss ----
    float mv = (tid < KPS) ? ss[tid] : -1e30f;
#pragma unroll
    for (int o = 16; o > 0; o >>= 1)
        mv = fmaxf(mv, __shfl_xor_sync(0xffffffffu, mv, o));
    if (lane == 0) wred[warp] = mv;
    __syncthreads();
    if (tid == 0) {
        float m = wred[0];
#pragma unroll
        for (int w = 1; w < 8; w++) m = fmaxf(m, wred[w]);
        wred[0] = m;
    }
    __syncthreads();
    const float m = wred[0];
    __syncthreads();

    float ev = 0.f;
    if (tid < KPS) {
        const float e = __expf(ss[tid] - m);
        ss[tid] = e;
        ev = e;
    }
#pragma unroll
    for (int o = 16; o > 0; o >>= 1)
        ev += __shfl_xor_sync(0xffffffffu, ev, o);
    if (lane == 0) wred[warp] = ev;
    __syncthreads();
    if (tid == 0) {
        float l = 0.f;
#pragma unroll
        for (int w = 0; w < 8; w++) l += wred[w];
        g_m[b * NSPLIT + split] = m;
        g_l[b * NSPLIT + split] = l;
    }
    __syncthreads();

    // ---- phase 2: partial = sum_k exp(s_k - m) * v[k][:] ----
    const float4* V4 = (const float4*)cache_v;
    const float4* base = V4 + (size_t)(b * KV + key0) * D4 + tid;
    float4 acc = make_float4(0.f, 0.f, 0.f, 0.f);
#pragma unroll 16
    for (int k = 0; k < KPS; k++) {
        const float  w = ss[k];
        const float4 v = base[(size_t)k * D4];
        acc.x += w * v.x; acc.y += w * v.y;
        acc.z += w * v.z; acc.w += w * v.w;
    }
    ((float4*)g_partial)[(size_t)(b * NSPLIT + split) * D4 + tid] = acc;
}

// ---------------- K2: global rescale + new-token term + round ----------------
// grid (4, B), block 256. Block covers 64 float4 columns; thread quads split NSPLIT.
__global__ void reduce_kernel(float* __restrict__ out) {
    const int b    = blockIdx.y;
    const int tid  = threadIdx.x;
    const int quad = tid >> 6;                    // 0..3  (16 splits each)
    const int c    = tid & 63;                    // local column
    const int col  = blockIdx.x * 64 + c;         // float4 column 0..255

    __shared__ float  red[256];
    __shared__ float  sc[NSPLIT];
    __shared__ float  s_wn;
    __shared__ float4 part[4][64];

    // new-key score: q . new_k / sqrt(D)
    {
        const float4 qq = ((const float4*)g_q )[b * D4 + tid];
        const float4 kk = ((const float4*)g_nk)[b * D4 + tid];
        red[tid] = qq.x * kk.x + qq.y * kk.y + qq.z * kk.z + qq.w * kk.w;
    }
    __syncthreads();
    for (int s = 128; s > 0; s >>= 1) {
        if (tid < s) red[tid] += red[tid + s];
        __syncthreads();
    }
    const float s_new = red[0] * 0.03125f;

    if (tid == 0) {
        float M = s_new;
#pragma unroll
        for (int s = 0; s < NSPLIT; s++) M = fmaxf(M, g_m[b * NSPLIT + s]);
        float L = __expf(s_new - M);
#pragma unroll
        for (int s = 0; s < NSPLIT; s++) {
            const float e = __expf(g_m[b * NSPLIT + s] - M);
            sc[s] = e;
            L += g_l[b * NSPLIT + s] * e;
        }
        const float inv = 1.f / L;
#pragma unroll
        for (int s = 0; s < NSPLIT; s++) sc[s] *= inv;
        s_wn = __expf(s_new - M) * inv;
    }
    __syncthreads();

    // each quad sums 16 splits for its column
    const float4* P4 = (const float4*)g_partial + (size_t)b * NSPLIT * D4 + col;
    float4 acc = make_float4(0.f, 0.f, 0.f, 0.f);
#pragma unroll
    for (int j = 0; j < 16; j++) {
        const int s = quad * 16 + j;
        const float  w = sc[s];
        const float4 p = P4[(size_t)s * D4];
        acc.x += w * p.x; acc.y += w * p.y;
        acc.z += w * p.z; acc.w += w * p.w;
    }
    part[quad][c] = acc;
    __syncthreads();

    if (quad == 0) {
        float4 a = part[0][c], p1 = part[1][c], p2 = part[2][c], p3 = part[3][c];
        a.x += p1.x + p2.x + p3.x;
        a.y += p1.y + p2.y + p3.y;
        a.z += p1.z + p2.z + p3.z;
        a.w += p1.w + p2.w + p3.w;

        const float wn = s_wn;
        const float4 nv = ((const float4*)g_nv)[b * D4 + col];
        a.x += wn * nv.x; a.y += wn * nv.y;
        a.z += wn * nv.z; a.w += wn * nv.w;

        a.x = rintf(a.x * 10000.f) / 10000.f;
        a.y = rintf(a.y * 10000.f) / 10000.f;
        a.z = rintf(a.z * 10000.f) / 10000.f;
        a.w = rintf(a.w * 10000.f) / 10000.f;
        ((float4*)out)[b * D4 + col] = a;
    }
}

// ---------------- launcher: fork kv_proj onto side stream, hidden under attn ----
extern "C" void kernel_launch(void* const* d_in, const int* in_sizes, int n_in,
                              void* d_out, int out_size) {
    const float* x  = (const float*)d_in[0];
    const float* ck = (const float*)d_in[1];
    const float* cv = (const float*)d_in[2];
    const float* wq = (const float*)d_in[3];
    const float* wk = (const float*)d_in[4];
    const float* wv = (const float*)d_in[5];
    float* out = (float*)d_out;

    // fork: side stream branches off the main (captured) stream
    cudaEventRecord(g_ev_fork, 0);
    cudaStreamWaitEvent(g_s2, g_ev_fork, 0);

    // side stream: k/v projections (only needed by reduce)
    kv_proj_kernel<<<dim3(128, 2), 256, 0, g_s2>>>(x, wk, wv);
    cudaEventRecord(g_ev_join, g_s2);

    // main stream: q projection, then the big attention pass
    q_proj_kernel<<<dim3(64, 2), 256>>>(x, wq);
    attn_kernel  <<<dim3(NSPLIT, B), 256>>>(ck, cv);

    // join, then final reduce
    cudaStreamWaitEvent(0, g_ev_join, 0);
    reduce_kernel<<<dim3(4, B), 256>>>(out);
}

// round 8
// speedup vs baseline: 1.0333x; 1.0153x over previous
#include <cuda_runtime.h>

#define B   16
#define KV  8192
#define D   1024
#define D4  256        // D / 4 (float4 per row)
#define NSPLIT 32      // KV splits
#define KPS (KV / NSPLIT)   // 256 keys per split

// ---------------- device scratch ----------------
__device__ float g_q [B * D];
__device__ float g_nk[B * D];
__device__ float g_nv[B * D];
__device__ float g_partial[B * NSPLIT * D];   // 2 MB, unnormalized V partials
__device__ float g_m[B * NSPLIT];             // local maxima
__device__ float g_l[B * NSPLIT];             // local exp-sums

// ---------------- stream/event for fork-join (created once, not device mem) ----
static cudaStream_t g_s2;
static cudaEvent_t  g_ev_fork, g_ev_join;
static struct StreamInit {
    StreamInit() {
        cudaStreamCreateWithFlags(&g_s2, cudaStreamNonBlocking);
        cudaEventCreateWithFlags(&g_ev_fork, cudaEventDisableTiming);
        cudaEventCreateWithFlags(&g_ev_join, cudaEventDisableTiming);
    }
} g_stream_init;

// ---------------- K0a: q projection (wq only) ----------------
// grid (64, 2), block 256 (8 warps). Each warp: 2 rows x 8 batches.
__global__ void q_proj_kernel(const float* __restrict__ x,
                              const float* __restrict__ wq) {
    __shared__ float4 xs[8 * D4];   // 8 batches of x, 32 KB
    const int tid  = threadIdx.x;
    const int warp = tid >> 5;
    const int lane = tid & 31;
    const int grp  = blockIdx.y;

    const float4* x4 = (const float4*)x;
    for (int i = tid; i < 8 * D4; i += 256) xs[i] = x4[grp * 8 * D4 + i];
    __syncthreads();

    const int eA = blockIdx.x * 16 + warp * 2;   // 0..1022 (even)
    const int eB = eA + 1;
    const float4* WA4 = (const float4*)wq + (size_t)eA * D4;
    const float4* WB4 = (const float4*)wq + (size_t)eB * D4;

    float accA[8], accB[8];
#pragma unroll
    for (int b = 0; b < 8; b++) { accA[b] = 0.f; accB[b] = 0.f; }

#pragma unroll
    for (int ii = 0; ii < 8; ii++) {
        const int i = lane + ii * 32;
        const float4 wa = WA4[i];
        const float4 wb = WB4[i];
#pragma unroll
        for (int b = 0; b < 8; b++) {
            const float4 xv = xs[b * D4 + i];
            accA[b] += wa.x * xv.x + wa.y * xv.y + wa.z * xv.z + wa.w * xv.w;
            accB[b] += wb.x * xv.x + wb.y * xv.y + wb.z * xv.z + wb.w * xv.w;
        }
    }
#pragma unroll
    for (int b = 0; b < 8; b++) {
#pragma unroll
        for (int o = 16; o > 0; o >>= 1) {
            accA[b] += __shfl_xor_sync(0xffffffffu, accA[b], o);
            accB[b] += __shfl_xor_sync(0xffffffffu, accB[b], o);
        }
    }
    if (lane == 0) {
#pragma unroll
        for (int b = 0; b < 8; b++) {
            g_q[(grp * 8 + b) * D + eA] = accA[b];
            g_q[(grp * 8 + b) * D + eB] = accB[b];
        }
    }
}

// ---------------- K0b: k/v projections (wk, wv) — runs concurrent with attn ----
// grid (128, 2), block 256 (8 warps). Each warp: 2 rows x 8 batches.
__global__ void kv_proj_kernel(const float* __restrict__ x,
                               const float* __restrict__ wk,
                               const float* __restrict__ wv) {
    __shared__ float4 xs[8 * D4];   // 8 batches of x, 32 KB
    const int tid  = threadIdx.x;
    const int warp = tid >> 5;
    const int lane = tid & 31;
    const int grp  = blockIdx.y;

    const float4* x4 = (const float4*)x;
    for (int i = tid; i < 8 * D4; i += 256) xs[i] = x4[grp * 8 * D4 + i];
    __syncthreads();

    const int rowA = blockIdx.x * 16 + warp * 2;   // 0..2046 (even)
    const int rowB = rowA + 1;
    const int matA = rowA >> 10, eA = rowA & 1023;
    const int matB = rowB >> 10, eB = rowB & 1023;
    const float* WA  = (matA == 0) ? wk   : wv;
    const float* WB  = (matB == 0) ? wk   : wv;
    float*      outA = (matA == 0) ? g_nk : g_nv;
    float*      outB = (matB == 0) ? g_nk : g_nv;
    const float4* WA4 = (const float4*)WA + (size_t)eA * D4;
    const float4* WB4 = (const float4*)WB + (size_t)eB * D4;

    float accA[8], accB[8];
#pragma unroll
    for (int b = 0; b < 8; b++) { accA[b] = 0.f; accB[b] = 0.f; }

#pragma unroll
    for (int ii = 0; ii < 8; ii++) {
        const int i = lane + ii * 32;
        const float4 wa = WA4[i];
        const float4 wb = WB4[i];
#pragma unroll
        for (int b = 0; b < 8; b++) {
            const float4 xv = xs[b * D4 + i];
            accA[b] += wa.x * xv.x + wa.y * xv.y + wa.z * xv.z + wa.w * xv.w;
            accB[b] += wb.x * xv.x + wb.y * xv.y + wb.z * xv.z + wb.w * xv.w;
        }
    }
#pragma unroll
    for (int b = 0; b < 8; b++) {
#pragma unroll
        for (int o = 16; o > 0; o >>= 1) {
            accA[b] += __shfl_xor_sync(0xffffffffu, accA[b], o);
            accB[b] += __shfl_xor_sync(0xffffffffu, accB[b], o);
        }
    }
    if (lane == 0) {
#pragma unroll
        for (int b = 0; b < 8; b++) {
            outA[(grp * 8 + b) * D + eA] = accA[b];
            outB[(grp * 8 + b) * D + eB] = accB[b];
        }
    }
}

// ---------------- K1: fused scores + local softmax + weighted AV partial ----------------
// grid (NSPLIT, B), block 256 (8 warps). Each block: 256 keys of one batch.
__global__ void attn_kernel(const float* __restrict__ cache_k,
                            const float* __restrict__ cache_v) {
    const int split = blockIdx.x;
    const int b     = blockIdx.y;
    const int tid   = threadIdx.x;
    const int warp  = tid >> 5;
    const int lane  = tid & 31;
    const int key0  = split * KPS;

    __shared__ float4 qs[D4];       // 4 KB
    __shared__ float  ss[KPS];      // scores -> exp weights (256)
    __shared__ float  wred[8];

    qs[tid] = ((const float4*)g_q)[b * D4 + tid];
    __syncthreads();

    // ---- phase 1: scores for 256 keys (32 per warp, 2-key ILP) ----
    const float4* K4 = (const float4*)cache_k;
    const int kw0 = warp * 32;
#pragma unroll 1
    for (int j = 0; j < 16; j++) {
        const int kA = kw0 + j;
        const int kB = kA + 16;
        const float4* rowA = K4 + (size_t)(b * KV + key0 + kA) * D4;
        const float4* rowB = K4 + (size_t)(b * KV + key0 + kB) * D4;
        float aA = 0.f, aB = 0.f;
#pragma unroll
        for (int ii = 0; ii < 8; ii++) {
            const int i = lane + ii * 32;
            const float4 qq = qs[i];
            const float4 ka = rowA[i];
            const float4 kb = rowB[i];
            aA += ka.x * qq.x + ka.y * qq.y + ka.z * qq.z + ka.w * qq.w;
            aB += kb.x * qq.x + kb.y * qq.y + kb.z * qq.z + kb.w * qq.w;
        }
#pragma unroll
        for (int o = 16; o > 0; o >>= 1) {
            aA += __shfl_xor_sync(0xffffffffu, aA, o);
            aB += __shfl_xor_sync(0xffffffffu, aB, o);
        }
        if (lane == 0) {
            ss[kA] = aA * 0.03125f;   // 1/sqrt(1024)
            ss[kB] = aB * 0.03125f;
        }
    }
    __syncthreads();

    // ---- local softmax stats: m = max, l = sum exp(s-m); exp stored in ss ----
    float mv = ss[tid];
#pragma unroll
    for (int o = 16; o > 0; o >>= 1)
        mv = fmaxf(mv, __shfl_xor_sync(0xffffffffu, mv, o));
    if (lane == 0) wred[warp] = mv;
    __syncthreads();
    if (tid == 0) {
        float m = wred[0];
#pragma unroll
        for (int w = 1; w < 8; w++) m = fmaxf(m, wred[w]);
        wred[0] = m;
    }
    __syncthreads();
    const float m = wred[0];
    __syncthreads();

    float ev;
    {
        const float e = __expf(ss[tid] - m);
        ss[tid] = e;
        ev = e;
    }
#pragma unroll
    for (int o = 16; o > 0; o >>= 1)
        ev += __shfl_xor_sync(0xffffffffu, ev, o);
    if (lane == 0) wred[warp] = ev;
    __syncthreads();
    if (tid == 0) {
        float l = 0.f;
#pragma unroll
        for (int w = 0; w < 8; w++) l += wred[w];
        g_m[b * NSPLIT + split] = m;
        g_l[b * NSPLIT + split] = l;
    }
    __syncthreads();

    // ---- phase 2: partial = sum_k exp(s_k - m) * v[k][:] ----
    const float4* V4 = (const float4*)cache_v;
    const float4* base = V4 + (size_t)(b * KV + key0) * D4 + tid;
    float4 acc = make_float4(0.f, 0.f, 0.f, 0.f);
#pragma unroll 16
    for (int k = 0; k < KPS; k++) {
        const float  w = ss[k];
        const float4 v = base[(size_t)k * D4];
        acc.x += w * v.x; acc.y += w * v.y;
        acc.z += w * v.z; acc.w += w * v.w;
    }
    ((float4*)g_partial)[(size_t)(b * NSPLIT + split) * D4 + tid] = acc;
}

// ---------------- K2: global rescale + new-token term + round ----------------
// grid (8, B), block 256. Block covers 32 float4 columns; 8 thread-groups split NSPLIT.
__global__ void reduce_kernel(float* __restrict__ out) {
    const int b   = blockIdx.y;
    const int tid = threadIdx.x;
    const int grpi = tid >> 5;                   // 0..7  (4 splits each)
    const int c    = tid & 31;                   // local column
    const int col  = blockIdx.x * 32 + c;        // float4 column 0..255

    __shared__ float  red[256];
    __shared__ float  sc[NSPLIT];
    __shared__ float  s_wn;
    __shared__ float4 part[8][32];

    // new-key score: q . new_k / sqrt(D)  (256 threads cover all 256 float4s)
    {
        const float4 qq = ((const float4*)g_q )[b * D4 + tid];
        const float4 kk = ((const float4*)g_nk)[b * D4 + tid];
        red[tid] = qq.x * kk.x + qq.y * kk.y + qq.z * kk.z + qq.w * kk.w;
    }
    __syncthreads();
    for (int s = 128; s > 0; s >>= 1) {
        if (tid < s) red[tid] += red[tid + s];
        __syncthreads();
    }
    const float s_new = red[0] * 0.03125f;

    if (tid == 0) {
        float M = s_new;
#pragma unroll
        for (int s = 0; s < NSPLIT; s++) M = fmaxf(M, g_m[b * NSPLIT + s]);
        float L = __expf(s_new - M);
#pragma unroll
        for (int s = 0; s < NSPLIT; s++) {
            const float e = __expf(g_m[b * NSPLIT + s] - M);
            sc[s] = e;
            L += g_l[b * NSPLIT + s] * e;
        }
        const float inv = 1.f / L;
#pragma unroll
        for (int s = 0; s < NSPLIT; s++) sc[s] *= inv;
        s_wn = __expf(s_new - M) * inv;
    }
    __syncthreads();

    // each group of 32 threads sums 4 splits for its column
    const float4* P4 = (const float4*)g_partial + (size_t)b * NSPLIT * D4 + col;
    float4 acc = make_float4(0.f, 0.f, 0.f, 0.f);
#pragma unroll
    for (int j = 0; j < 4; j++) {
        const int s = grpi * 4 + j;
        const float  w = sc[s];
        const float4 p = P4[(size_t)s * D4];
        acc.x += w * p.x; acc.y += w * p.y;
        acc.z += w * p.z; acc.w += w * p.w;
    }
    part[grpi][c] = acc;
    __syncthreads();

    if (grpi == 0) {
        float4 a = part[0][c];
#pragma unroll
        for (int g = 1; g < 8; g++) {
            const float4 p = part[g][c];
            a.x += p.x; a.y += p.y; a.z += p.z; a.w += p.w;
        }
        const float wn = s_wn;
        const float4 nv = ((const float4*)g_nv)[b * D4 + col];
        a.x += wn * nv.x; a.y += wn * nv.y;
        a.z += wn * nv.z; a.w += wn * nv.w;

        a.x = rintf(a.x * 10000.f) / 10000.f;
        a.y = rintf(a.y * 10000.f) / 10000.f;
        a.z = rintf(a.z * 10000.f) / 10000.f;
        a.w = rintf(a.w * 10000.f) / 10000.f;
        ((float4*)out)[b * D4 + col] = a;
    }
}

// ---------------- launcher: fork kv_proj onto side stream, hidden under attn ----
extern "C" void kernel_launch(void* const* d_in, const int* in_sizes, int n_in,
                              void* d_out, int out_size) {
    const float* x  = (const float*)d_in[0];
    const float* ck = (const float*)d_in[1];
    const float* cv = (const float*)d_in[2];
    const float* wq = (const float*)d_in[3];
    const float* wk = (const float*)d_in[4];
    const float* wv = (const float*)d_in[5];
    float* out = (float*)d_out;

    // fork: side stream branches off the main (captured) stream
    cudaEventRecord(g_ev_fork, 0);
    cudaStreamWaitEvent(g_s2, g_ev_fork, 0);

    // side stream: k/v projections (only needed by reduce)
    kv_proj_kernel<<<dim3(128, 2), 256, 0, g_s2>>>(x, wk, wv);
    cudaEventRecord(g_ev_join, g_s2);

    // main stream: q projection, then the big attention pass
    q_proj_kernel<<<dim3(64, 2), 256>>>(x, wq);
    attn_kernel  <<<dim3(NSPLIT, B), 256>>>(ck, cv);

    // join, then final reduce
    cudaStreamWaitEvent(0, g_ev_join, 0);
    reduce_kernel<<<dim3(8, B), 256>>>(out);
}

// round 9
// speedup vs baseline: 1.0481x; 1.0143x over previous
#include <cuda_runtime.h>

#define B   16
#define KV  8192
#define D   1024
#define D4  256        // D / 4 (float4 per row)
#define NSPLIT 32      // KV splits
#define KPS (KV / NSPLIT)   // 256 keys per split

// ---------------- device scratch ----------------
__device__ float g_q [B * D];
__device__ float g_nk[B * D];
__device__ float g_nv[B * D];
__device__ float g_partial[B * NSPLIT * D];   // 2 MB, unnormalized V partials
__device__ float g_m[B * NSPLIT];             // local maxima
__device__ float g_l[B * NSPLIT];             // local exp-sums

// ---------------- stream/event for fork-join (created once, not device mem) ----
static cudaStream_t g_s2;
static cudaEvent_t  g_ev_fork, g_ev_join;
static struct StreamInit {
    StreamInit() {
        cudaStreamCreateWithFlags(&g_s2, cudaStreamNonBlocking);
        cudaEventCreateWithFlags(&g_ev_fork, cudaEventDisableTiming);
        cudaEventCreateWithFlags(&g_ev_join, cudaEventDisableTiming);
    }
} g_stream_init;

// ---------------- K0a: q projection (wq only) ----------------
// grid (64, 2), block 256 (8 warps). Each warp: 2 rows x 8 batches.
__global__ void q_proj_kernel(const float* __restrict__ x,
                              const float* __restrict__ wq) {
    __shared__ float4 xs[8 * D4];   // 8 batches of x, 32 KB
    const int tid  = threadIdx.x;
    const int warp = tid >> 5;
    const int lane = tid & 31;
    const int grp  = blockIdx.y;

    const float4* x4 = (const float4*)x;
    for (int i = tid; i < 8 * D4; i += 256) xs[i] = x4[grp * 8 * D4 + i];
    __syncthreads();

    const int eA = blockIdx.x * 16 + warp * 2;   // 0..1022 (even)
    const int eB = eA + 1;
    const float4* WA4 = (const float4*)wq + (size_t)eA * D4;
    const float4* WB4 = (const float4*)wq + (size_t)eB * D4;

    float accA[8], accB[8];
#pragma unroll
    for (int b = 0; b < 8; b++) { accA[b] = 0.f; accB[b] = 0.f; }

#pragma unroll
    for (int ii = 0; ii < 8; ii++) {
        const int i = lane + ii * 32;
        const float4 wa = WA4[i];
        const float4 wb = WB4[i];
#pragma unroll
        for (int b = 0; b < 8; b++) {
            const float4 xv = xs[b * D4 + i];
            accA[b] += wa.x * xv.x + wa.y * xv.y + wa.z * xv.z + wa.w * xv.w;
            accB[b] += wb.x * xv.x + wb.y * xv.y + wb.z * xv.z + wb.w * xv.w;
        }
    }
#pragma unroll
    for (int b = 0; b < 8; b++) {
#pragma unroll
        for (int o = 16; o > 0; o >>= 1) {
            accA[b] += __shfl_xor_sync(0xffffffffu, accA[b], o);
            accB[b] += __shfl_xor_sync(0xffffffffu, accB[b], o);
        }
    }
    if (lane == 0) {
#pragma unroll
        for (int b = 0; b < 8; b++) {
            g_q[(grp * 8 + b) * D + eA] = accA[b];
            g_q[(grp * 8 + b) * D + eB] = accB[b];
        }
    }
}

// ---------------- K0b: k/v projections (wk, wv) — runs concurrent with attn ----
// grid (128, 2), block 256 (8 warps). Each warp: 2 rows x 8 batches.
__global__ void kv_proj_kernel(const float* __restrict__ x,
                               const float* __restrict__ wk,
                               const float* __restrict__ wv) {
    __shared__ float4 xs[8 * D4];   // 8 batches of x, 32 KB
    const int tid  = threadIdx.x;
    const int warp = tid >> 5;
    const int lane = tid & 31;
    const int grp  = blockIdx.y;

    const float4* x4 = (const float4*)x;
    for (int i = tid; i < 8 * D4; i += 256) xs[i] = x4[grp * 8 * D4 + i];
    __syncthreads();

    const int rowA = blockIdx.x * 16 + warp * 2;   // 0..2046 (even)
    const int rowB = rowA + 1;
    const int matA = rowA >> 10, eA = rowA & 1023;
    const int matB = rowB >> 10, eB = rowB & 1023;
    const float* WA  = (matA == 0) ? wk   : wv;
    const float* WB  = (matB == 0) ? wk   : wv;
    float*      outA = (matA == 0) ? g_nk : g_nv;
    float*      outB = (matB == 0) ? g_nk : g_nv;
    const float4* WA4 = (const float4*)WA + (size_t)eA * D4;
    const float4* WB4 = (const float4*)WB + (size_t)eB * D4;

    float accA[8], accB[8];
#pragma unroll
    for (int b = 0; b < 8; b++) { accA[b] = 0.f; accB[b] = 0.f; }

#pragma unroll
    for (int ii = 0; ii < 8; ii++) {
        const int i = lane + ii * 32;
        const float4 wa = WA4[i];
        const float4 wb = WB4[i];
#pragma unroll
        for (int b = 0; b < 8; b++) {
            const float4 xv = xs[b * D4 + i];
            accA[b] += wa.x * xv.x + wa.y * xv.y + wa.z * xv.z + wa.w * xv.w;
            accB[b] += wb.x * xv.x + wb.y * xv.y + wb.z * xv.z + wb.w * xv.w;
        }
    }
#pragma unroll
    for (int b = 0; b < 8; b++) {
#pragma unroll
        for (int o = 16; o > 0; o >>= 1) {
            accA[b] += __shfl_xor_sync(0xffffffffu, accA[b], o);
            accB[b] += __shfl_xor_sync(0xffffffffu, accB[b], o);
        }
    }
    if (lane == 0) {
#pragma unroll
        for (int b = 0; b < 8; b++) {
            outA[(grp * 8 + b) * D + eA] = accA[b];
            outB[(grp * 8 + b) * D + eB] = accB[b];
        }
    }
}

// ---------------- K1: fused scores + local softmax + weighted AV partial ----------------
// grid (NSPLIT, B), block 256 (8 warps). Each block: 256 keys of one batch.
__global__ void attn_kernel(const float* __restrict__ cache_k,
                            const float* __restrict__ cache_v) {
    const int split = blockIdx.x;
    const int b     = blockIdx.y;
    const int tid   = threadIdx.x;
    const int warp  = tid >> 5;
    const int lane  = tid & 31;
    const int key0  = split * KPS;

    __shared__ float4 qs[D4];       // 4 KB
    __shared__ float  ss[KPS];      // scores -> exp weights (256)
    __shared__ float  wred[8];

    qs[tid] = ((const float4*)g_q)[b * D4 + tid];
    __syncthreads();

    // ---- phase 1: scores for 256 keys (32 per warp, 2-key ILP) ----
    const float4* K4 = (const float4*)cache_k;
    const int kw0 = warp * 32;
#pragma unroll 1
    for (int j = 0; j < 16; j++) {
        const int kA = kw0 + j;
        const int kB = kA + 16;
        const float4* rowA = K4 + (size_t)(b * KV + key0 + kA) * D4;
        const float4* rowB = K4 + (size_t)(b * KV + key0 + kB) * D4;
        float aA = 0.f, aB = 0.f;
#pragma unroll
        for (int ii = 0; ii < 8; ii++) {
            const int i = lane + ii * 32;
            const float4 qq = qs[i];
            const float4 ka = rowA[i];
            const float4 kb = rowB[i];
            aA += ka.x * qq.x + ka.y * qq.y + ka.z * qq.z + ka.w * qq.w;
            aB += kb.x * qq.x + kb.y * qq.y + kb.z * qq.z + kb.w * qq.w;
        }
#pragma unroll
        for (int o = 16; o > 0; o >>= 1) {
            aA += __shfl_xor_sync(0xffffffffu, aA, o);
            aB += __shfl_xor_sync(0xffffffffu, aB, o);
        }
        if (lane == 0) {
            ss[kA] = aA * 0.03125f;   // 1/sqrt(1024)
            ss[kB] = aB * 0.03125f;
        }
    }
    __syncthreads();

    // ---- local softmax stats: m = max, l = sum exp(s-m); exp stored in ss ----
    float mv = ss[tid];
#pragma unroll
    for (int o = 16; o > 0; o >>= 1)
        mv = fmaxf(mv, __shfl_xor_sync(0xffffffffu, mv, o));
    if (lane == 0) wred[warp] = mv;
    __syncthreads();
    if (tid == 0) {
        float m = wred[0];
#pragma unroll
        for (int w = 1; w < 8; w++) m = fmaxf(m, wred[w]);
        wred[0] = m;
    }
    __syncthreads();
    const float m = wred[0];
    __syncthreads();

    float ev;
    {
        const float e = __expf(ss[tid] - m);
        ss[tid] = e;
        ev = e;
    }
#pragma unroll
    for (int o = 16; o > 0; o >>= 1)
        ev += __shfl_xor_sync(0xffffffffu, ev, o);
    if (lane == 0) wred[warp] = ev;
    __syncthreads();
    if (tid == 0) {
        float l = 0.f;
#pragma unroll
        for (int w = 0; w < 8; w++) l += wred[w];
        g_m[b * NSPLIT + split] = m;
        g_l[b * NSPLIT + split] = l;
    }
    __syncthreads();

    // ---- phase 2: partial = sum_k exp(s_k - m) * v[k][:] ----
    const float4* V4 = (const float4*)cache_v;
    const float4* base = V4 + (size_t)(b * KV + key0) * D4 + tid;
    float4 acc = make_float4(0.f, 0.f, 0.f, 0.f);
#pragma unroll 16
    for (int k = 0; k < KPS; k++) {
        const float  w = ss[k];
        const float4 v = base[(size_t)k * D4];
        acc.x += w * v.x; acc.y += w * v.y;
        acc.z += w * v.z; acc.w += w * v.w;
    }
    ((float4*)g_partial)[(size_t)(b * NSPLIT + split) * D4 + tid] = acc;
}

// ---------------- K2: global rescale + new-token term + round ----------------
// grid (16, B), block 256. Block covers 16 float4 columns; 16 groups x 2 splits.
// All softmax-combine math parallelized across lanes (no serial tid==0 section).
__global__ void reduce_kernel(float* __restrict__ out) {
    const int b    = blockIdx.y;
    const int tid  = threadIdx.x;
    const int grpi = tid >> 4;                   // 0..15  (2 splits each)
    const int c    = tid & 15;                   // local column
    const int col  = blockIdx.x * 16 + c;        // float4 column 0..255

    __shared__ float  wred[8];
    __shared__ float  sc[NSPLIT];
    __shared__ float  s_wn_sh;
    __shared__ float4 part[16][16];

    // ---- parallel new-key score: q . new_k / sqrt(D) ----
    {
        const float4 qq = ((const float4*)g_q )[b * D4 + tid];
        const float4 kk = ((const float4*)g_nk)[b * D4 + tid];
        float p = qq.x * kk.x + qq.y * kk.y + qq.z * kk.z + qq.w * kk.w;
#pragma unroll
        for (int o = 16; o > 0; o >>= 1)
            p += __shfl_xor_sync(0xffffffffu, p, o);
        if ((tid & 31) == 0) wred[tid >> 5] = p;
    }
    __syncthreads();

    // ---- lanes 0..31: each owns one split; combine stats fully in-warp ----
    if (tid < 32) {
        float sn = (tid < 8) ? wred[tid] : 0.f;
#pragma unroll
        for (int o = 4; o > 0; o >>= 1)
            sn += __shfl_xor_sync(0xffffffffu, sn, o);
        sn = __shfl_sync(0xffffffffu, sn, 0) * 0.03125f;   // s_new

        const float ms = g_m[b * NSPLIT + tid];
        const float ls = g_l[b * NSPLIT + tid];
        float M = fmaxf(ms, sn);
#pragma unroll
        for (int o = 16; o > 0; o >>= 1)
            M = fmaxf(M, __shfl_xor_sync(0xffffffffu, M, o));

        const float e = __expf(ms - M);
        float L = ls * e;
#pragma unroll
        for (int o = 16; o > 0; o >>= 1)
            L += __shfl_xor_sync(0xffffffffu, L, o);
        const float en = __expf(sn - M);
        const float inv = 1.f / (L + en);

        sc[tid] = e * inv;
        if (tid == 0) s_wn_sh = en * inv;
    }
    __syncthreads();

    // ---- each 16-thread group sums 2 splits for its column ----
    const float4* P4 = (const float4*)g_partial + (size_t)b * NSPLIT * D4 + col;
    float4 acc;
    {
        const int s0 = grpi * 2;
        const float w0 = sc[s0], w1 = sc[s0 + 1];
        const float4 p0 = P4[(size_t)s0 * D4];
        const float4 p1 = P4[(size_t)(s0 + 1) * D4];
        acc.x = w0 * p0.x + w1 * p1.x;
        acc.y = w0 * p0.y + w1 * p1.y;
        acc.z = w0 * p0.z + w1 * p1.z;
        acc.w = w0 * p0.w + w1 * p1.w;
    }
    part[grpi][c] = acc;
    __syncthreads();

    if (grpi == 0) {
        float4 a = part[0][c];
#pragma unroll
        for (int g = 1; g < 16; g++) {
            const float4 p = part[g][c];
            a.x += p.x; a.y += p.y; a.z += p.z; a.w += p.w;
        }
        const float wn = s_wn_sh;
        const float4 nv = ((const float4*)g_nv)[b * D4 + col];
        a.x += wn * nv.x; a.y += wn * nv.y;
        a.z += wn * nv.z; a.w += wn * nv.w;

        a.x = rintf(a.x * 10000.f) / 10000.f;
        a.y = rintf(a.y * 10000.f) / 10000.f;
        a.z = rintf(a.z * 10000.f) / 10000.f;
        a.w = rintf(a.w * 10000.f) / 10000.f;
        ((float4*)out)[b * D4 + col] = a;
    }
}

// ---------------- launcher: fork kv_proj onto side stream, hidden under attn ----
extern "C" void kernel_launch(void* const* d_in, const int* in_sizes, int n_in,
                              void* d_out, int out_size) {
    const float* x  = (const float*)d_in[0];
    const float* ck = (const float*)d_in[1];
    const float* cv = (const float*)d_in[2];
    const float* wq = (const float*)d_in[3];
    const float* wk = (const float*)d_in[4];
    const float* wv = (const float*)d_in[5];
    float* out = (float*)d_out;

    // fork: side stream branches off the main (captured) stream
    cudaEventRecord(g_ev_fork, 0);
    cudaStreamWaitEvent(g_s2, g_ev_fork, 0);

    // side stream: k/v projections (only needed by reduce)
    kv_proj_kernel<<<dim3(128, 2), 256, 0, g_s2>>>(x, wk, wv);
    cudaEventRecord(g_ev_join, g_s2);

    // main stream: q projection, then the big attention pass
    q_proj_kernel<<<dim3(64, 2), 256>>>(x, wq);
    attn_kernel  <<<dim3(NSPLIT, B), 256>>>(ck, cv);

    // join, then final reduce
    cudaStreamWaitEvent(0, g_ev_join, 0);
    reduce_kernel<<<dim3(16, B), 256>>>(out);
}